// round 1
// baseline (speedup 1.0000x reference)
#include <cuda_runtime.h>
#include <math.h>

#define SEQ   2048
#define EMB   1024
#define NH    16
#define HD    64
#define BATCH 2
#define MROWS (BATCH*SEQ)   // 4096

// ---------------- scratch (allocation-free rule: device globals) ----------------
__device__ float g_q[(size_t)BATCH*NH*SEQ*HD];     // [B,H,S,D]
__device__ float g_k[(size_t)BATCH*NH*SEQ*HD];
__device__ float g_v[(size_t)BATCH*NH*SEQ*HD];
__device__ float g_attn[(size_t)MROWS*EMB];        // [B*S, E]

// =================================================================
// GEMM: C = A[M,K] @ W[N,K]^T + bias[N]
// 128x128 tile, BK=8, 256 threads, 8x8 register micro-tile.
// scatter=0: C row-major [M,N]; scatter=1: write into [B,H,S,D] layout.
// =================================================================
__global__ __launch_bounds__(256) void gemm_bias_kernel(
    const float* __restrict__ A, const float* __restrict__ W,
    const float* __restrict__ bias, float* __restrict__ C,
    int M, int N, int K, int scatter)
{
    __shared__ float As[8 * 132];
    __shared__ float Bs[8 * 132];

    const int tid = threadIdx.x;
    const int tx = tid & 15;       // 0..15 -> col group
    const int ty = tid >> 4;       // 0..15 -> row group

    const float* Ab = A + (size_t)(blockIdx.y * 128) * K;
    const float* Wb = W + (size_t)(blockIdx.x * 128) * K;

    const int lr = tid >> 1;          // 0..127
    const int lc = (tid & 1) * 4;     // 0 or 4

    float acc[8][8];
#pragma unroll
    for (int i = 0; i < 8; i++)
#pragma unroll
        for (int j = 0; j < 8; j++) acc[i][j] = 0.0f;

    for (int k0 = 0; k0 < K; k0 += 8) {
        float4 av = *(const float4*)(Ab + (size_t)lr * K + k0 + lc);
        float4 wv = *(const float4*)(Wb + (size_t)lr * K + k0 + lc);
        __syncthreads();
        As[(lc + 0) * 132 + lr] = av.x;
        As[(lc + 1) * 132 + lr] = av.y;
        As[(lc + 2) * 132 + lr] = av.z;
        As[(lc + 3) * 132 + lr] = av.w;
        Bs[(lc + 0) * 132 + lr] = wv.x;
        Bs[(lc + 1) * 132 + lr] = wv.y;
        Bs[(lc + 2) * 132 + lr] = wv.z;
        Bs[(lc + 3) * 132 + lr] = wv.w;
        __syncthreads();

#pragma unroll
        for (int kk = 0; kk < 8; kk++) {
            float4 a0 = *(const float4*)&As[kk * 132 + ty * 8];
            float4 a1 = *(const float4*)&As[kk * 132 + ty * 8 + 4];
            float4 b0 = *(const float4*)&Bs[kk * 132 + tx * 8];
            float4 b1 = *(const float4*)&Bs[kk * 132 + tx * 8 + 4];
            float a[8] = {a0.x, a0.y, a0.z, a0.w, a1.x, a1.y, a1.z, a1.w};
            float b[8] = {b0.x, b0.y, b0.z, b0.w, b1.x, b1.y, b1.z, b1.w};
#pragma unroll
            for (int i = 0; i < 8; i++)
#pragma unroll
                for (int j = 0; j < 8; j++)
                    acc[i][j] = fmaf(a[i], b[j], acc[i][j]);
        }
    }

    const int col0 = blockIdx.x * 128 + tx * 8;
    float4 bb0 = *(const float4*)&bias[col0];
    float4 bb1 = *(const float4*)&bias[col0 + 4];
    const float bc[8] = {bb0.x, bb0.y, bb0.z, bb0.w, bb1.x, bb1.y, bb1.z, bb1.w};

#pragma unroll
    for (int i = 0; i < 8; i++) {
        int row = blockIdx.y * 128 + ty * 8 + i;
        float4 o0 = make_float4(acc[i][0] + bc[0], acc[i][1] + bc[1],
                                acc[i][2] + bc[2], acc[i][3] + bc[3]);
        float4 o1 = make_float4(acc[i][4] + bc[4], acc[i][5] + bc[5],
                                acc[i][6] + bc[6], acc[i][7] + bc[7]);
        if (!scatter) {
            float* p = C + (size_t)row * N + col0;
            *(float4*)p = o0;
            *(float4*)(p + 4) = o1;
        } else {
            // row = b*SEQ + s ; col = h*HD + d  ->  [B,H,S,D]
            int b = row >> 11;            // SEQ = 2048
            int s = row & (SEQ - 1);
            int h = col0 >> 6;            // HD = 64 (col0..col0+7 same head)
            int d = col0 & (HD - 1);
            float* p = C + ((size_t)((b * NH + h) * SEQ + s)) * HD + d;
            *(float4*)p = o0;
            *(float4*)(p + 4) = o1;
        }
    }
}

// =================================================================
// Flash-attention fp32: per block = one (b,h) x 64-row Q tile.
// Transposed K/Q/P smem tiles with XOR swizzle: conflict-free LDS.128 reads.
// =================================================================
__device__ __forceinline__ int xsw(int row, int col) {
    // 64x64 fp32 tile, stride 64, 4-float-unit XOR swizzle on (row>>2)
    return (row << 6) + ((((col >> 2) ^ ((row >> 2) & 15)) << 2) + (col & 3));
}

__global__ __launch_bounds__(256) void attn_kernel(
    const float* __restrict__ Q, const float* __restrict__ K,
    const float* __restrict__ V, float* __restrict__ O)
{
    extern __shared__ float sm[];
    float* Qs = sm;              // 4096 floats, transposed-swizzled (d, r)
    float* Ks = sm + 4096;       // transposed-swizzled (d, c)
    float* Ps = sm + 8192;       // transposed-swizzled (kv, r)
    float* Vs = sm + 12288;      // natural (kv, d)

    const int tid = threadIdx.x;
    const int tx = tid & 15;     // col group  (kv cols / d cols)
    const int ty = tid >> 4;     // row group  (q rows)
    const int bh = blockIdx.y;   // b*NH + h

    const float* Qb = Q + ((size_t)bh * SEQ + blockIdx.x * 64) * HD;
    const float* Kb = K + (size_t)bh * SEQ * HD;
    const float* Vb = V + (size_t)bh * SEQ * HD;

    // load Q tile transposed + pre-scaled by 1/sqrt(D)
#pragma unroll
    for (int it = 0; it < 4; it++) {
        int idx = tid + it * 256;
        int r = idx >> 4;
        int c = idx & 15;
        float4 qv = *(const float4*)(Qb + r * HD + c * 4);
        Qs[xsw(c * 4 + 0, r)] = qv.x * 0.125f;
        Qs[xsw(c * 4 + 1, r)] = qv.y * 0.125f;
        Qs[xsw(c * 4 + 2, r)] = qv.z * 0.125f;
        Qs[xsw(c * 4 + 3, r)] = qv.w * 0.125f;
    }

    float mI[4], lI[4], oacc[4][4];
#pragma unroll
    for (int i = 0; i < 4; i++) {
        mI[i] = -1e30f;
        lI[i] = 0.0f;
#pragma unroll
        for (int j = 0; j < 4; j++) oacc[i][j] = 0.0f;
    }

    for (int t = 0; t < SEQ / 64; t++) {
        __syncthreads();   // prior iteration done reading Ks/Vs/Ps
        const float* Kt = Kb + (size_t)t * 64 * HD;
        const float* Vt = Vb + (size_t)t * 64 * HD;
#pragma unroll
        for (int it = 0; it < 4; it++) {
            int idx = tid + it * 256;
            int r = idx >> 4;
            int c = idx & 15;
            float4 kv4 = *(const float4*)(Kt + r * HD + c * 4);
            Ks[xsw(c * 4 + 0, r)] = kv4.x;
            Ks[xsw(c * 4 + 1, r)] = kv4.y;
            Ks[xsw(c * 4 + 2, r)] = kv4.z;
            Ks[xsw(c * 4 + 3, r)] = kv4.w;
            float4 vv = *(const float4*)(Vt + r * HD + c * 4);
            *(float4*)&Vs[r * 64 + c * 4] = vv;
        }
        __syncthreads();

        // ---- S = Q K^T (pre-scaled) ----
        float s[4][4];
#pragma unroll
        for (int i = 0; i < 4; i++)
#pragma unroll
            for (int j = 0; j < 4; j++) s[i][j] = 0.0f;

#pragma unroll 8
        for (int d = 0; d < 64; d++) {
            float4 qf = *(const float4*)&Qs[xsw(d, ty * 4)];
            float4 kf = *(const float4*)&Ks[xsw(d, tx * 4)];
            float qa[4] = {qf.x, qf.y, qf.z, qf.w};
            float ka[4] = {kf.x, kf.y, kf.z, kf.w};
#pragma unroll
            for (int i = 0; i < 4; i++)
#pragma unroll
                for (int j = 0; j < 4; j++)
                    s[i][j] = fmaf(qa[i], ka[j], s[i][j]);
        }

        // ---- online softmax (row stats across the 16 tx lanes) ----
#pragma unroll
        for (int i = 0; i < 4; i++) {
            float rm = fmaxf(fmaxf(s[i][0], s[i][1]), fmaxf(s[i][2], s[i][3]));
            rm = fmaxf(rm, __shfl_xor_sync(0xffffffffu, rm, 1));
            rm = fmaxf(rm, __shfl_xor_sync(0xffffffffu, rm, 2));
            rm = fmaxf(rm, __shfl_xor_sync(0xffffffffu, rm, 4));
            rm = fmaxf(rm, __shfl_xor_sync(0xffffffffu, rm, 8));
            float mnew = fmaxf(mI[i], rm);
            float alpha = __expf(mI[i] - mnew);
            float rs = 0.0f;
#pragma unroll
            for (int j = 0; j < 4; j++) {
                s[i][j] = __expf(s[i][j] - mnew);
                rs += s[i][j];
            }
            rs += __shfl_xor_sync(0xffffffffu, rs, 1);
            rs += __shfl_xor_sync(0xffffffffu, rs, 2);
            rs += __shfl_xor_sync(0xffffffffu, rs, 4);
            rs += __shfl_xor_sync(0xffffffffu, rs, 8);
            lI[i] = lI[i] * alpha + rs;
            mI[i] = mnew;
#pragma unroll
            for (int j = 0; j < 4; j++) oacc[i][j] *= alpha;
        }

        // ---- store P transposed-swizzled ----
#pragma unroll
        for (int i = 0; i < 4; i++)
#pragma unroll
            for (int j = 0; j < 4; j++)
                Ps[xsw(tx * 4 + j, ty * 4 + i)] = s[i][j];
        __syncthreads();

        // ---- O += P V ----
#pragma unroll 8
        for (int kv = 0; kv < 64; kv++) {
            float4 pf = *(const float4*)&Ps[xsw(kv, ty * 4)];
            float4 vf = *(const float4*)&Vs[kv * 64 + tx * 4];
            float pa[4] = {pf.x, pf.y, pf.z, pf.w};
            float va[4] = {vf.x, vf.y, vf.z, vf.w};
#pragma unroll
            for (int i = 0; i < 4; i++)
#pragma unroll
                for (int j = 0; j < 4; j++)
                    oacc[i][j] = fmaf(pa[i], va[j], oacc[i][j]);
        }
    }

    // ---- epilogue: normalize, write [B,S,E] ----
    const int b = bh >> 4;
    const int h = bh & (NH - 1);
#pragma unroll
    for (int i = 0; i < 4; i++) {
        float inv = 1.0f / lI[i];
        int sg = blockIdx.x * 64 + ty * 4 + i;
        float4 o = make_float4(oacc[i][0] * inv, oacc[i][1] * inv,
                               oacc[i][2] * inv, oacc[i][3] * inv);
        float* p = O + ((size_t)(b * SEQ + sg)) * EMB + h * HD + tx * 4;
        *(float4*)p = o;
    }
}

// =================================================================
extern "C" void kernel_launch(void* const* d_in, const int* in_sizes, int n_in,
                              void* d_out, int out_size)
{
    const float* x  = (const float*)d_in[0];
    const float* wq = (const float*)d_in[1];
    const float* bq = (const float*)d_in[2];
    const float* wk = (const float*)d_in[3];
    const float* bk = (const float*)d_in[4];
    const float* wv = (const float*)d_in[5];
    const float* bv = (const float*)d_in[6];
    const float* wo = (const float*)d_in[7];
    const float* bo = (const float*)d_in[8];
    float* out = (float*)d_out;

    void *pq, *pk, *pv, *pa;
    cudaGetSymbolAddress(&pq, g_q);
    cudaGetSymbolAddress(&pk, g_k);
    cudaGetSymbolAddress(&pv, g_v);
    cudaGetSymbolAddress(&pa, g_attn);

    dim3 gg(EMB / 128, MROWS / 128);   // (8, 32)
    gemm_bias_kernel<<<gg, 256>>>(x, wq, bq, (float*)pq, MROWS, EMB, EMB, 1);
    gemm_bias_kernel<<<gg, 256>>>(x, wk, bk, (float*)pk, MROWS, EMB, EMB, 1);
    gemm_bias_kernel<<<gg, 256>>>(x, wv, bv, (float*)pv, MROWS, EMB, EMB, 1);

    const int smem = 4 * 64 * 64 * sizeof(float);   // 64 KB
    cudaFuncSetAttribute(attn_kernel, cudaFuncAttributeMaxDynamicSharedMemorySize, smem);
    dim3 ga(SEQ / 64, BATCH * NH);     // (32, 32)
    attn_kernel<<<ga, 256, smem>>>((const float*)pq, (const float*)pk,
                                   (const float*)pv, (float*)pa);

    gemm_bias_kernel<<<gg, 256>>>((const float*)pa, wo, bo, out, MROWS, EMB, EMB, 0);
}

// round 2
// speedup vs baseline: 2.4193x; 2.4193x over previous
#include <cuda_runtime.h>
#include <math.h>

#define SEQ   2048
#define EMB   1024
#define NH    16
#define HD    64
#define BATCH 2
#define MROWS (BATCH*SEQ)   // 4096

// ---------------- scratch (allocation-free rule: device globals) ----------------
__device__ float g_q[(size_t)BATCH*NH*SEQ*HD];     // [B,H,S,D]
__device__ float g_k[(size_t)BATCH*NH*SEQ*HD];
__device__ float g_v[(size_t)BATCH*NH*SEQ*HD];
__device__ float g_attn[(size_t)MROWS*EMB];        // [B*S, E]

// ---------------- tf32 helpers ----------------
__device__ __forceinline__ unsigned f2tf(float x) {
    unsigned u;
    asm("cvt.rna.tf32.f32 %0, %1;" : "=r"(u) : "f"(x));
    return u;
}

__device__ __forceinline__ void mma8(float* d, const unsigned* a, const unsigned* b) {
    asm volatile(
        "mma.sync.aligned.m16n8k8.row.col.f32.tf32.tf32.f32 "
        "{%0,%1,%2,%3},{%4,%5,%6,%7},{%8,%9},{%0,%1,%2,%3};"
        : "+f"(d[0]), "+f"(d[1]), "+f"(d[2]), "+f"(d[3])
        : "r"(a[0]), "r"(a[1]), "r"(a[2]), "r"(a[3]), "r"(b[0]), "r"(b[1]));
}

// =================================================================
// tf32 tensor-core GEMM: C = A[M,K] @ W[N,K]^T + bias[N]
// 128x128 tile, BK=16, 256 threads, 8 warps of 32x64.
// scatter=0: C row-major [M,EMB]; scatter=1: write into [B,H,S,D].
// =================================================================
#define GBK 16
#define GST 20   // smem row stride (floats): (20*r + c) % 32 distinct -> conflict-free frags

__global__ __launch_bounds__(256) void gemm_tc(
    const float* __restrict__ A, const float* __restrict__ W,
    const float* __restrict__ bias, float* __restrict__ C, int scatter)
{
    __shared__ float As[2][128 * GST];
    __shared__ float Bs[2][128 * GST];

    const int tid = threadIdx.x;
    const int lane = tid & 31;
    const int wid = tid >> 5;
    const int wm = (wid & 3) * 32;     // warp m offset
    const int wn = (wid >> 2) * 64;    // warp n offset
    const int brow = blockIdx.y * 128;
    const int bcol = blockIdx.x * 128;
    const int K = EMB;
    const int r0 = lane >> 2;
    const int c4 = lane & 3;

    // global-load mapping: row = tid>>1 (0..127), 8 contiguous cols at (tid&1)*8
    const int lrow = tid >> 1;
    const int lcol = (tid & 1) * 8;
    const float* Ag = A + (size_t)(brow + lrow) * K + lcol;
    const float* Wg = W + (size_t)(bcol + lrow) * K + lcol;

    float4 ar0, ar1, br0, br1;
    auto LDG = [&](int t) {
        const float* a = Ag + t * GBK;
        ar0 = *(const float4*)a;       ar1 = *(const float4*)(a + 4);
        const float* w = Wg + t * GBK;
        br0 = *(const float4*)w;       br1 = *(const float4*)(w + 4);
    };
    auto STS = [&](int b) {
        float* pa = &As[b][lrow * GST + lcol];
        pa[0] = __uint_as_float(f2tf(ar0.x)); pa[1] = __uint_as_float(f2tf(ar0.y));
        pa[2] = __uint_as_float(f2tf(ar0.z)); pa[3] = __uint_as_float(f2tf(ar0.w));
        pa[4] = __uint_as_float(f2tf(ar1.x)); pa[5] = __uint_as_float(f2tf(ar1.y));
        pa[6] = __uint_as_float(f2tf(ar1.z)); pa[7] = __uint_as_float(f2tf(ar1.w));
        float* pb = &Bs[b][lrow * GST + lcol];
        pb[0] = __uint_as_float(f2tf(br0.x)); pb[1] = __uint_as_float(f2tf(br0.y));
        pb[2] = __uint_as_float(f2tf(br0.z)); pb[3] = __uint_as_float(f2tf(br0.w));
        pb[4] = __uint_as_float(f2tf(br1.x)); pb[5] = __uint_as_float(f2tf(br1.y));
        pb[6] = __uint_as_float(f2tf(br1.z)); pb[7] = __uint_as_float(f2tf(br1.w));
    };

    float acc[2][8][4];
#pragma unroll
    for (int i = 0; i < 2; i++)
#pragma unroll
        for (int j = 0; j < 8; j++)
#pragma unroll
            for (int q = 0; q < 4; q++) acc[i][j][q] = 0.0f;

    const int T = K / GBK;   // 64
    LDG(0);
    STS(0);
    __syncthreads();
    int buf = 0;

    for (int t = 0; t < T; t++) {
        if (t + 1 < T) LDG(t + 1);
#pragma unroll
        for (int kk = 0; kk < 2; kk++) {
            unsigned af[2][4];
#pragma unroll
            for (int i = 0; i < 2; i++) {
                const float* base = &As[buf][(wm + 16 * i) * GST + kk * 8];
                af[i][0] = __float_as_uint(base[r0 * GST + c4]);
                af[i][1] = __float_as_uint(base[(r0 + 8) * GST + c4]);
                af[i][2] = __float_as_uint(base[r0 * GST + c4 + 4]);
                af[i][3] = __float_as_uint(base[(r0 + 8) * GST + c4 + 4]);
            }
#pragma unroll
            for (int j = 0; j < 8; j++) {
                const float* bb = &Bs[buf][(wn + 8 * j) * GST + kk * 8];
                unsigned bf[2];
                bf[0] = __float_as_uint(bb[r0 * GST + c4]);
                bf[1] = __float_as_uint(bb[r0 * GST + c4 + 4]);
                mma8(acc[0][j], af[0], bf);
                mma8(acc[1][j], af[1], bf);
            }
        }
        if (t + 1 < T) {
            STS(buf ^ 1);
            __syncthreads();
            buf ^= 1;
        }
    }

    // bias cache
    float bc[8][2];
#pragma unroll
    for (int j = 0; j < 8; j++) {
        int col = bcol + wn + 8 * j + 2 * c4;
        bc[j][0] = bias[col];
        bc[j][1] = bias[col + 1];
    }

#pragma unroll
    for (int i = 0; i < 2; i++) {
        int row = brow + wm + 16 * i + r0;
#pragma unroll
        for (int j = 0; j < 8; j++) {
            int col = bcol + wn + 8 * j + 2 * c4;
            float2 v0 = make_float2(acc[i][j][0] + bc[j][0], acc[i][j][1] + bc[j][1]);
            float2 v1 = make_float2(acc[i][j][2] + bc[j][0], acc[i][j][3] + bc[j][1]);
            if (!scatter) {
                *(float2*)&C[(size_t)row * EMB + col] = v0;
                *(float2*)&C[(size_t)(row + 8) * EMB + col] = v1;
            } else {
                int b = row >> 11;
                int s = row & (SEQ - 1);
                int h = col >> 6;
                int d = col & (HD - 1);
                float* p = C + ((size_t)((b * NH + h) * SEQ + s)) * HD + d;
                *(float2*)p = v0;
                float* p2 = C + ((size_t)((b * NH + h) * SEQ + s + 8)) * HD + d;
                *(float2*)p2 = v1;
            }
        }
    }
}

// =================================================================
// Flash attention, tf32 tensor cores.
// Block: 256 threads (8 warps), 128 Q rows, 64-wide KV tiles.
// Warp w owns Q rows [16w, 16w+16): softmax fully warp-local.
// =================================================================
#define QST 68   // (68*r + c)%32 == (4r+c): conflict-free for frag pattern
#define VST 72   // (72*k + n)%32 == (8k+n): conflict-free for V B-frags

__global__ __launch_bounds__(256) void attn_tc(
    const float* __restrict__ Q, const float* __restrict__ K,
    const float* __restrict__ V, float* __restrict__ O)
{
    extern __shared__ float sm[];
    float* Qs = sm;                     // 128*QST
    float* Ks = Qs + 128 * QST;         // 64*QST
    float* Vs = Ks + 64 * QST;          // 64*VST
    float* Ps = Vs + 64 * VST;          // 128*QST

    const int tid = threadIdx.x;
    const int lane = tid & 31;
    const int wid = tid >> 5;
    const int r0 = lane >> 2;
    const int c4 = lane & 3;
    const int bh = blockIdx.y;
    const int qt = blockIdx.x;

    const float* Qb = Q + ((size_t)bh * SEQ + qt * 128) * HD;
    const float* Kb = K + (size_t)bh * SEQ * HD;
    const float* Vb = V + (size_t)bh * SEQ * HD;

    // load Q tile (scaled by 1/sqrt(D)=0.125, cvt to tf32)
    {
        int r = tid >> 1, c0 = (tid & 1) * 32;
        const float* src = Qb + r * HD + c0;
        float* dst = Qs + r * QST + c0;
#pragma unroll
        for (int c = 0; c < 8; c++) {
            float4 v = *(const float4*)(src + 4 * c);
            float4 o4;
            o4.x = __uint_as_float(f2tf(v.x * 0.125f));
            o4.y = __uint_as_float(f2tf(v.y * 0.125f));
            o4.z = __uint_as_float(f2tf(v.z * 0.125f));
            o4.w = __uint_as_float(f2tf(v.w * 0.125f));
            *(float4*)(dst + 4 * c) = o4;
        }
    }

    // KV global staging: row = tid>>2 (0..63), 16 cols at (tid&3)*16
    const int kvr = tid >> 2;
    const int kvc = (tid & 3) * 16;
    float4 kreg[4], vreg[4];
    auto LDKV = [&](int t) {
        const float* ks = Kb + (size_t)(t * 64 + kvr) * HD + kvc;
        const float* vs = Vb + (size_t)(t * 64 + kvr) * HD + kvc;
#pragma unroll
        for (int c = 0; c < 4; c++) {
            kreg[c] = *(const float4*)(ks + 4 * c);
            vreg[c] = *(const float4*)(vs + 4 * c);
        }
    };
    LDKV(0);

    float m0 = -1e30f, m1 = -1e30f, l0 = 0.0f, l1 = 0.0f;
    float o[8][4];
#pragma unroll
    for (int j = 0; j < 8; j++)
#pragma unroll
        for (int q = 0; q < 4; q++) o[j][q] = 0.0f;

    for (int t = 0; t < SEQ / 64; t++) {
        __syncthreads();   // everyone done reading Ks/Vs from previous tile
        {
            float* kd = Ks + kvr * QST + kvc;
            float* vd = Vs + kvr * VST + kvc;
#pragma unroll
            for (int c = 0; c < 4; c++) {
                float4 kc, vc;
                kc.x = __uint_as_float(f2tf(kreg[c].x));
                kc.y = __uint_as_float(f2tf(kreg[c].y));
                kc.z = __uint_as_float(f2tf(kreg[c].z));
                kc.w = __uint_as_float(f2tf(kreg[c].w));
                vc.x = __uint_as_float(f2tf(vreg[c].x));
                vc.y = __uint_as_float(f2tf(vreg[c].y));
                vc.z = __uint_as_float(f2tf(vreg[c].z));
                vc.w = __uint_as_float(f2tf(vreg[c].w));
                *(float4*)(kd + 4 * c) = kc;
                *(float4*)(vd + 4 * c) = vc;
            }
        }
        __syncthreads();
        if (t + 1 < SEQ / 64) LDKV(t + 1);

        // ---- S = Q K^T ----
        float s[8][4];
#pragma unroll
        for (int j = 0; j < 8; j++)
#pragma unroll
            for (int q = 0; q < 4; q++) s[j][q] = 0.0f;

#pragma unroll
        for (int kk = 0; kk < 8; kk++) {
            unsigned af[4];
            const float* qb2 = Qs + (16 * wid) * QST + kk * 8;
            af[0] = __float_as_uint(qb2[r0 * QST + c4]);
            af[1] = __float_as_uint(qb2[(r0 + 8) * QST + c4]);
            af[2] = __float_as_uint(qb2[r0 * QST + c4 + 4]);
            af[3] = __float_as_uint(qb2[(r0 + 8) * QST + c4 + 4]);
#pragma unroll
            for (int j = 0; j < 8; j++) {
                const float* kb2 = Ks + (8 * j) * QST + kk * 8;
                unsigned bf[2];
                bf[0] = __float_as_uint(kb2[r0 * QST + c4]);
                bf[1] = __float_as_uint(kb2[r0 * QST + c4 + 4]);
                mma8(s[j], af, bf);
            }
        }

        // ---- online softmax (rows r0 -> half0: s[j][0..1], r0+8 -> half1) ----
        float rm0 = -1e30f, rm1 = -1e30f;
#pragma unroll
        for (int j = 0; j < 8; j++) {
            rm0 = fmaxf(rm0, fmaxf(s[j][0], s[j][1]));
            rm1 = fmaxf(rm1, fmaxf(s[j][2], s[j][3]));
        }
        rm0 = fmaxf(rm0, __shfl_xor_sync(0xffffffffu, rm0, 1));
        rm0 = fmaxf(rm0, __shfl_xor_sync(0xffffffffu, rm0, 2));
        rm1 = fmaxf(rm1, __shfl_xor_sync(0xffffffffu, rm1, 1));
        rm1 = fmaxf(rm1, __shfl_xor_sync(0xffffffffu, rm1, 2));
        float mn0 = fmaxf(m0, rm0), mn1 = fmaxf(m1, rm1);
        float a0 = __expf(m0 - mn0), a1 = __expf(m1 - mn1);
        m0 = mn0; m1 = mn1;
        float rs0 = 0.0f, rs1 = 0.0f;
#pragma unroll
        for (int j = 0; j < 8; j++) {
            s[j][0] = __expf(s[j][0] - mn0);
            s[j][1] = __expf(s[j][1] - mn0);
            s[j][2] = __expf(s[j][2] - mn1);
            s[j][3] = __expf(s[j][3] - mn1);
            rs0 += s[j][0] + s[j][1];
            rs1 += s[j][2] + s[j][3];
        }
        rs0 += __shfl_xor_sync(0xffffffffu, rs0, 1);
        rs0 += __shfl_xor_sync(0xffffffffu, rs0, 2);
        rs1 += __shfl_xor_sync(0xffffffffu, rs1, 1);
        rs1 += __shfl_xor_sync(0xffffffffu, rs1, 2);
        l0 = l0 * a0 + rs0;
        l1 = l1 * a1 + rs1;
#pragma unroll
        for (int j = 0; j < 8; j++) {
            o[j][0] *= a0; o[j][1] *= a0;
            o[j][2] *= a1; o[j][3] *= a1;
        }

        // ---- store P (tf32) for A-fragment reload; warp-local rows only ----
#pragma unroll
        for (int j = 0; j < 8; j++) {
            float* pd = Ps + (16 * wid + r0) * QST + 8 * j + 2 * c4;
            pd[0] = __uint_as_float(f2tf(s[j][0]));
            pd[1] = __uint_as_float(f2tf(s[j][1]));
            float* pd2 = Ps + (16 * wid + r0 + 8) * QST + 8 * j + 2 * c4;
            pd2[0] = __uint_as_float(f2tf(s[j][2]));
            pd2[1] = __uint_as_float(f2tf(s[j][3]));
        }
        __syncwarp();

        // ---- O += P V ----
#pragma unroll
        for (int kk = 0; kk < 8; kk++) {
            unsigned af[4];
            const float* pb = Ps + (16 * wid) * QST + kk * 8;
            af[0] = __float_as_uint(pb[r0 * QST + c4]);
            af[1] = __float_as_uint(pb[(r0 + 8) * QST + c4]);
            af[2] = __float_as_uint(pb[r0 * QST + c4 + 4]);
            af[3] = __float_as_uint(pb[(r0 + 8) * QST + c4 + 4]);
#pragma unroll
            for (int j = 0; j < 8; j++) {
                const float* vb2 = Vs + (kk * 8) * VST + 8 * j;
                unsigned bf[2];
                bf[0] = __float_as_uint(vb2[c4 * VST + r0]);
                bf[1] = __float_as_uint(vb2[(c4 + 4) * VST + r0]);
                mma8(o[j], af, bf);
            }
        }
    }

    // ---- epilogue: normalize, write [B,S,E] ----
    float inv0 = 1.0f / l0, inv1 = 1.0f / l1;
    const int b = bh >> 4;
    const int h = bh & (NH - 1);
    const int s0 = qt * 128 + 16 * wid + r0;
#pragma unroll
    for (int j = 0; j < 8; j++) {
        int col = h * HD + 8 * j + 2 * c4;
        float* p = O + ((size_t)(b * SEQ + s0)) * EMB + col;
        *(float2*)p = make_float2(o[j][0] * inv0, o[j][1] * inv0);
        float* p2 = O + ((size_t)(b * SEQ + s0 + 8)) * EMB + col;
        *(float2*)p2 = make_float2(o[j][2] * inv1, o[j][3] * inv1);
    }
}

// =================================================================
extern "C" void kernel_launch(void* const* d_in, const int* in_sizes, int n_in,
                              void* d_out, int out_size)
{
    const float* x  = (const float*)d_in[0];
    const float* wq = (const float*)d_in[1];
    const float* bq = (const float*)d_in[2];
    const float* wk = (const float*)d_in[3];
    const float* bk = (const float*)d_in[4];
    const float* wv = (const float*)d_in[5];
    const float* bv = (const float*)d_in[6];
    const float* wo = (const float*)d_in[7];
    const float* bo = (const float*)d_in[8];
    float* out = (float*)d_out;

    void *pq, *pk, *pv, *pa;
    cudaGetSymbolAddress(&pq, g_q);
    cudaGetSymbolAddress(&pk, g_k);
    cudaGetSymbolAddress(&pv, g_v);
    cudaGetSymbolAddress(&pa, g_attn);

    dim3 gg(EMB / 128, MROWS / 128);   // (8, 32)
    gemm_tc<<<gg, 256>>>(x, wq, bq, (float*)pq, 1);
    gemm_tc<<<gg, 256>>>(x, wk, bk, (float*)pk, 1);
    gemm_tc<<<gg, 256>>>(x, wv, bv, (float*)pv, 1);

    const int smem = (128 * QST + 64 * QST + 64 * VST + 128 * QST) * sizeof(float);
    cudaFuncSetAttribute(attn_tc, cudaFuncAttributeMaxDynamicSharedMemorySize, smem);
    dim3 ga(SEQ / 128, BATCH * NH);    // (16, 32)
    attn_tc<<<ga, 256, smem>>>((const float*)pq, (const float*)pk,
                               (const float*)pv, (float*)pa);

    gemm_tc<<<gg, 256>>>((const float*)pa, wo, bo, out, 0);
}